// round 3
// baseline (speedup 1.0000x reference)
#include <cuda_runtime.h>
#include <math.h>

#define SEQ   256
#define BATCH 64
#define XD    64
#define FEATD 256
#define DECD  256
#define HD    512
#define KTOT  (FEATD + HD)   // 768
#define NG    128            // gate blocks
#define NF    8              // feat/output blocks
#define NB    (NG + NF)      // 136 total (<= 148 SMs -> all co-resident)

// ---------------- persistent device scratch ---------------------------------
__device__ float g_feat_tf[SEQ * BATCH * FEATD];   // precomputed teacher-forced feats
__device__ float g_act[2][BATCH * KTOT];           // [feat(256) | h(512)] double buffered
__device__ float g_dec[BATCH * DECD];
__device__ float g_yprev[BATCH * XD];
__device__ unsigned int g_bar_ct;

__device__ __forceinline__ float sig_(float x) { return 1.0f / (1.0f + expf(-x)); }

// software grid barrier: monotonic counter, pure L2 poll (NO nanosleep --
// nanosleep wakeup quantization was costing ~15-20us/barrier in R2)
__device__ __forceinline__ void gsync(unsigned int target) {
    __syncthreads();
    if (threadIdx.x == 0) {
        __threadfence();
        atomicAdd(&g_bar_ct, 1u);
        while (*(volatile unsigned int*)&g_bar_ct < target) { }
    }
    __syncthreads();
}

// ---------------- k_init: zero act[0] h-part, reset barrier ------------------
__global__ void k_init() {
    int i = blockIdx.x * blockDim.x + threadIdx.x;
    if (i == 0) g_bar_ct = 0u;
    if (i < BATCH * KTOT) g_act[0][i] = 0.0f;
}

// ---------------- k_feat_tf: all teacher-forced features (one shot) ----------
__global__ void k_feat_tf(const float* __restrict__ x,
                          const float* __restrict__ Wfx,
                          const float* __restrict__ bfx) {
    int tb = blockIdx.x;
    int f  = threadIdx.x;
    const float* xr = x + tb * XD;
    const float* w  = Wfx + f * XD;
    float s = bfx[f];
#pragma unroll
    for (int k = 0; k < XD; k++) s += xr[k] * w[k];
    g_feat_tf[tb * FEATD + f] = tanhf(s);
}

// ---------------- persistent kernel: all 256 steps ---------------------------
// blocks 0..127 (G): phase1 = Whh*h part of gates (K=512) + dec (2 cols);
//                    phase2 = Wih*feat part (K=256) + activation/state update
// blocks 128..135 (F): phase1 feat blend (32 cols each), phase2 y_t (8 cols each)
__global__ void __launch_bounds__(256, 1)
k_persist(const float* __restrict__ Wih, const float* __restrict__ Whh,
          const float* __restrict__ bih, const float* __restrict__ bhh,
          const float* __restrict__ Whx, const float* __restrict__ bhx,
          const float* __restrict__ Wfx, const float* __restrict__ bfx,
          const float* __restrict__ Wout, const float* __restrict__ bout,
          const float* __restrict__ ms, float* __restrict__ out) {
    extern __shared__ float smem[];
    const int blk = blockIdx.x;
    const int tid = threadIdx.x;

    if (blk < NG) {
        // ======================= G block ====================================
        float* w_s   = smem;                     // [KTOT][16] gate weights, 48KB
        float* wdec  = smem + KTOT * 16;         // [2][HD] dec weights, 4KB
        float* g_ex  = wdec + 2 * HD;            // [64][16] gate exchange, 4KB

        const int n0 = blk * 4;                  // first h-unit owned
        // stage gate weights once: column lc = gate*4 + unit
        for (int idx = tid; idx < KTOT * 16; idx += 256) {
            int k  = idx >> 4;
            int lc = idx & 15;
            int gi = lc >> 2;
            int u  = lc & 3;
            int j  = gi * HD + n0 + u;
            w_s[idx] = (k < FEATD) ? Wih[j * FEATD + k] : Whh[j * HD + (k - FEATD)];
        }
        // stage dec weight rows 2*blk, 2*blk+1 (contiguous)
        for (int idx = tid; idx < 2 * HD; idx += 256)
            wdec[idx] = Whx[2 * blk * HD + idx];

        const int b  = tid >> 2;                 // batch 0..63
        const int cg = tid & 3;                  // gate (i,f,g,o)
        const int jb = cg * HD + n0;
        const float bb0 = bih[jb + 0] + bhh[jb + 0];
        const float bb1 = bih[jb + 1] + bhh[jb + 1];
        const float bb2 = bih[jb + 2] + bhh[jb + 2];
        const float bb3 = bih[jb + 3] + bhh[jb + 3];
        float c_reg = 0.0f;                      // cell state for (b, unit n0+cg)
        __syncthreads();

        for (int t = 0; t < SEQ; t++) {
            const int p = t & 1;

            // ---- phase 1a: Whh*h(t) contribution to gates (K=512) ----------
            float a0 = bb0, a1 = bb1, a2 = bb2, a3 = bb3;
            {
                const float4* hv = (const float4*)(&g_act[p][b * KTOT + FEATD]);
#pragma unroll 4
                for (int kk = 0; kk < HD / 4; kk++) {
                    float4 av = __ldcg(hv + kk);
                    int kb = FEATD + kk * 4;
                    float4 w0 = *(const float4*)&w_s[(kb + 0) * 16 + cg * 4];
                    float4 w1 = *(const float4*)&w_s[(kb + 1) * 16 + cg * 4];
                    float4 w2 = *(const float4*)&w_s[(kb + 2) * 16 + cg * 4];
                    float4 w3 = *(const float4*)&w_s[(kb + 3) * 16 + cg * 4];
                    a0 += av.x * w0.x; a1 += av.x * w0.y; a2 += av.x * w0.z; a3 += av.x * w0.w;
                    a0 += av.y * w1.x; a1 += av.y * w1.y; a2 += av.y * w1.z; a3 += av.y * w1.w;
                    a0 += av.z * w2.x; a1 += av.z * w2.y; a2 += av.z * w2.z; a3 += av.z * w2.w;
                    a0 += av.w * w3.x; a1 += av.w * w3.y; a2 += av.w * w3.z; a3 += av.w * w3.w;
                }
            }
            // ---- phase 1b: dec cols 2*blk, 2*blk+1 -------------------------
            if (tid < 128) {
                int b1 = tid & 63;
                int ci = tid >> 6;
                const float4* hv = (const float4*)(&g_act[p][b1 * KTOT + FEATD]);
                const float4* wv = (const float4*)(wdec + ci * HD);
                float s0 = 0.f, s1 = 0.f, s2 = 0.f, s3 = 0.f;
#pragma unroll 8
                for (int k = 0; k < HD / 4; k++) {
                    float4 h4 = __ldcg(hv + k);
                    float4 w4 = wv[k];
                    s0 += h4.x * w4.x; s1 += h4.y * w4.y;
                    s2 += h4.z * w4.z; s3 += h4.w * w4.w;
                }
                int c = 2 * blk + ci;
                float s = (s0 + s1) + (s2 + s3) + bhx[c];
                __stcg(&g_dec[b1 * DECD + c], tanhf(s));
            }
            gsync((unsigned)(2 * t + 1) * NB);

            // ---- phase 2: Wih*feat(t) part of gates (K=256) ----------------
            {
                const float4* fv = (const float4*)(&g_act[p][b * KTOT]);
#pragma unroll 4
                for (int kk = 0; kk < FEATD / 4; kk++) {
                    float4 av = __ldcg(fv + kk);
                    int kb = kk * 4;
                    float4 w0 = *(const float4*)&w_s[(kb + 0) * 16 + cg * 4];
                    float4 w1 = *(const float4*)&w_s[(kb + 1) * 16 + cg * 4];
                    float4 w2 = *(const float4*)&w_s[(kb + 2) * 16 + cg * 4];
                    float4 w3 = *(const float4*)&w_s[(kb + 3) * 16 + cg * 4];
                    a0 += av.x * w0.x; a1 += av.x * w0.y; a2 += av.x * w0.z; a3 += av.x * w0.w;
                    a0 += av.y * w1.x; a1 += av.y * w1.y; a2 += av.y * w1.z; a3 += av.y * w1.w;
                    a0 += av.z * w2.x; a1 += av.z * w2.y; a2 += av.z * w2.z; a3 += av.z * w2.w;
                    a0 += av.w * w3.x; a1 += av.w * w3.y; a2 += av.w * w3.z; a3 += av.w * w3.w;
                }
            }
            g_ex[b * 16 + cg * 4 + 0] = a0;
            g_ex[b * 16 + cg * 4 + 1] = a1;
            g_ex[b * 16 + cg * 4 + 2] = a2;
            g_ex[b * 16 + cg * 4 + 3] = a3;
            __syncthreads();
            {
                int u = cg;                      // this thread owns unit n0+u
                float i_v = g_ex[b * 16 + 0  + u];
                float f_v = g_ex[b * 16 + 4  + u];
                float gg  = g_ex[b * 16 + 8  + u];
                float o_v = g_ex[b * 16 + 12 + u];
                float c_new = sig_(f_v) * c_reg + sig_(i_v) * tanhf(gg);
                float h_new = sig_(o_v) * tanhf(c_new);
                c_reg = c_new;
                __stcg(&g_act[p ^ 1][b * KTOT + FEATD + n0 + u], h_new);
            }
            gsync((unsigned)(2 * t + 2) * NB);
        }
    } else {
        // ======================= F block ====================================
        const int f = blk - NG;
        float* wfx_s  = smem;                    // [32][64]  feat weight slice, 8KB
        float* wout_s = smem + 32 * XD;          // [8][256]  out weight slice, 8KB
        for (int idx = tid; idx < 32 * XD; idx += 256)
            wfx_s[idx] = Wfx[f * 32 * XD + idx];
        for (int idx = tid; idx < 8 * DECD; idx += 256)
            wout_s[idx] = Wout[f * 8 * DECD + idx];

        const int b  = tid & 63;
        const int ci = tid >> 6;                 // 0..3
        __syncthreads();

        for (int t = 0; t < SEQ; t++) {
            const int p = t & 1;
            // ---- phase 1: feat blend (cols f*32 .. f*32+31) ----------------
            {
                float yr[XD];
                if (t > 0) {
                    const float4* yv = (const float4*)(&g_yprev[b * XD]);
#pragma unroll
                    for (int k = 0; k < XD / 4; k++) {
                        float4 v = __ldcg(yv + k);
                        yr[4 * k] = v.x; yr[4 * k + 1] = v.y;
                        yr[4 * k + 2] = v.z; yr[4 * k + 3] = v.w;
                    }
                }
                float m = ms[t];
#pragma unroll
                for (int q = 0; q < 8; q++) {
                    int cl = ci * 8 + q;
                    int c  = f * 32 + cl;
                    float ftf = __ldg(&g_feat_tf[(t * BATCH + b) * FEATD + c]);
                    float outv;
                    if (t == 0) {
                        outv = ftf;
                    } else {
                        float s = bfx[c];
                        const float* w = wfx_s + cl * XD;
#pragma unroll
                        for (int k = 0; k < XD; k++) s += yr[k] * w[k];
                        float fa = tanhf(s);
                        outv = m * fa + (1.0f - m) * ftf;
                    }
                    __stcg(&g_act[p][b * KTOT + c], outv);
                }
            }
            gsync((unsigned)(2 * t + 1) * NB);

            // ---- phase 2: y_t (cols f*8 .. f*8+7) --------------------------
            {
                const float4* dv = (const float4*)(&g_dec[b * DECD]);
#pragma unroll
                for (int q = 0; q < 2; q++) {
                    int cl = ci * 2 + q;
                    int c  = f * 8 + cl;
                    const float4* wv = (const float4*)(wout_s + cl * DECD);
                    float s0 = 0.f, s1 = 0.f, s2 = 0.f, s3 = 0.f;
#pragma unroll 8
                    for (int k = 0; k < DECD / 4; k++) {
                        float4 d4 = __ldcg(dv + k);
                        float4 w4 = wv[k];
                        s0 += d4.x * w4.x; s1 += d4.y * w4.y;
                        s2 += d4.z * w4.z; s3 += d4.w * w4.w;
                    }
                    float s = (s0 + s1) + (s2 + s3) + bout[c];
                    out[(t * BATCH + b) * XD + c] = s;
                    __stcg(&g_yprev[b * XD + c], s);
                }
            }
            gsync((unsigned)(2 * t + 2) * NB);
        }
    }
}

// ---------------------------------------------------------------------------
extern "C" void kernel_launch(void* const* d_in, const int* in_sizes, int n_in,
                              void* d_out, int out_size) {
    const float* x    = (const float*)d_in[0];
    const float* ms   = (const float*)d_in[1];
    const float* Wfx  = (const float*)d_in[2];
    const float* bfx  = (const float*)d_in[3];
    const float* Wih  = (const float*)d_in[4];
    const float* Whh  = (const float*)d_in[5];
    const float* bih  = (const float*)d_in[6];
    const float* bhh  = (const float*)d_in[7];
    const float* Whx  = (const float*)d_in[8];
    const float* bhx  = (const float*)d_in[9];
    const float* Wout = (const float*)d_in[10];
    const float* bout = (const float*)d_in[11];
    float* out = (float*)d_out;

    const int smem_p = (KTOT * 16 + 2 * HD + 64 * 16) * sizeof(float);  // 57344 B
    static bool attr_set = false;
    if (!attr_set) {
        cudaFuncSetAttribute(k_persist, cudaFuncAttributeMaxDynamicSharedMemorySize, smem_p);
        attr_set = true;
    }

    k_init<<<(BATCH * KTOT + 255) / 256, 256>>>();
    k_feat_tf<<<SEQ * BATCH, FEATD>>>(x, Wfx, bfx);
    k_persist<<<NB, 256, smem_p>>>(Wih, Whh, bih, bhh, Whx, bhx,
                                   Wfx, bfx, Wout, bout, ms, out);
}

// round 5
// speedup vs baseline: 2.0145x; 2.0145x over previous
#include <cuda_runtime.h>
#include <math.h>

#define SEQ   256
#define BATCH 64
#define XD    64
#define FEATD 256
#define DECD  256
#define HD    512
#define KTOT  (FEATD + HD)   // 768
#define NG    128
#define NF    8
#define NB    (NG + NF)      // 136 blocks, all co-resident

// ---------------- persistent device scratch ---------------------------------
__device__ float g_feat_tf[SEQ * BATCH * FEATD];
__device__ float g_act[2][BATCH * KTOT];     // [feat(256) | h(512)]
__device__ float g_dec[BATCH * DECD];
__device__ float g_yprev[BATCH * XD];
__device__ unsigned int g_bar;

__device__ __forceinline__ float sig_(float x) { return 1.0f / (1.0f + expf(-x)); }

__device__ __forceinline__ void ffma2(unsigned long long& acc,
                                      unsigned long long a, unsigned long long b) {
    asm("fma.rn.f32x2 %0, %1, %2, %0;" : "+l"(acc) : "l"(a), "l"(b));
}
__device__ __forceinline__ float pairsum(unsigned long long v) {
    float lo, hi;
    asm("mov.b64 {%0,%1}, %2;" : "=f"(lo), "=f"(hi) : "l"(v));
    return lo + hi;
}
__device__ __forceinline__ unsigned long long pack2(float lo, float hi) {
    unsigned long long v;
    asm("mov.b64 %0, {%1,%2};" : "=l"(v) : "f"(lo), "f"(hi));
    return v;
}

// grid barrier: arrive once, poll with light nanosleep backoff
__device__ __forceinline__ void gsync(unsigned int target) {
    __syncthreads();
    if (threadIdx.x == 0) {
        __threadfence();
        atomicAdd(&g_bar, 1u);
        while (*(volatile unsigned int*)&g_bar < target) __nanosleep(40);
    }
    __syncthreads();
}

__global__ void k_reset() { g_bar = 0u; }

// smem: floats. G: wpair[384*32]=12288 | wdec[2*512]=1024 | g_ex[64*16]=1024 | xs[64]
//       F: wfx_s[32*64]=2048 | wout_s[8*256]=2048 | ... | xs at 14336
#define SM_FLOATS 14400
#define XS_OFF    14336

__global__ void __launch_bounds__(256, 1)
k_persist(const float* __restrict__ x,   const float* __restrict__ ms,
          const float* __restrict__ Wfx, const float* __restrict__ bfx,
          const float* __restrict__ Wih, const float* __restrict__ Whh,
          const float* __restrict__ bih, const float* __restrict__ bhh,
          const float* __restrict__ Whx, const float* __restrict__ bhx,
          const float* __restrict__ Wout,const float* __restrict__ bout,
          float* __restrict__ out) {
    extern __shared__ float smem[];
    const int blk = blockIdx.x;
    const int tid = threadIdx.x;
    const int wid = tid >> 5;
    const int l   = tid & 31;
    unsigned int bar_n = 0;

    // ===================== prologue: feat_tf (all blocks) ====================
    {
        float wreg[XD];
        const float4* wf4 = (const float4*)(Wfx + tid * XD);
#pragma unroll
        for (int i = 0; i < XD / 4; i++) ((float4*)wreg)[i] = __ldg(wf4 + i);
        float biasf = __ldg(&bfx[tid]);
        float* xs = smem + XS_OFF;
        for (int r = blk; r < SEQ * BATCH; r += NB) {
            __syncthreads();
            if (tid < 16) ((float4*)xs)[tid] = __ldg((const float4*)(x + r * XD) + tid);
            __syncthreads();
            float s = biasf;
#pragma unroll
            for (int k = 0; k < XD; k++) s += xs[k] * wreg[k];
            g_feat_tf[r * FEATD + tid] = tanhf(s);
        }
        __syncthreads();
    }

    if (blk < NG) {
        // ========================== G block =================================
        float* w_s  = smem;                   // paired gate weights [384][16][2]
        float* wdec = smem + KTOT * 16;       // [2][512]
        float* g_ex = wdec + 2 * HD;          // [64][16]
        const int n0 = blk * 4;

        for (int idx = tid; idx < KTOT * 16; idx += 256) {
            int k  = idx >> 4;
            int lc = idx & 15;
            int gi = lc >> 2;
            int u  = lc & 3;
            int j  = gi * HD + n0 + u;
            float v = (k < FEATD) ? Wih[j * FEATD + k] : Whh[j * HD + (k - FEATD)];
            w_s[(k >> 1) * 32 + lc * 2 + (k & 1)] = v;
        }
        for (int idx = tid; idx < 2 * HD; idx += 256)
            wdec[idx] = Whx[2 * blk * HD + idx];

        const int b  = tid >> 2;
        const int cg = tid & 3;
        const int jb = cg * HD + n0;
        const float bb0 = __ldg(&bih[jb + 0]) + __ldg(&bhh[jb + 0]);
        const float bb1 = __ldg(&bih[jb + 1]) + __ldg(&bhh[jb + 1]);
        const float bb2 = __ldg(&bih[jb + 2]) + __ldg(&bhh[jb + 2]);
        const float bb3 = __ldg(&bih[jb + 3]) + __ldg(&bhh[jb + 3]);
        float c_reg = 0.0f;
        // zero h(0)
        __stcg(&g_act[0][b * KTOT + FEATD + n0 + cg], 0.0f);

        gsync((++bar_n) * NB);   // prologue barrier

        for (int t = 0; t < SEQ; t++) {
            const int p = t & 1;

            // ---- phase 1a: gate . h(t)  (K=512, paired) --------------------
            unsigned long long acc0 = pack2(bb0, 0.f), acc1 = pack2(bb1, 0.f);
            unsigned long long acc2 = pack2(bb2, 0.f), acc3 = pack2(bb3, 0.f);
            {
                const ulonglong2* hv = (const ulonglong2*)(g_act[p] + b * KTOT + FEATD);
#pragma unroll 8
                for (int i = 0; i < HD / 4; i++) {      // 4 k per iter (2 pairs)
                    ulonglong2 av = __ldcg(hv + i);
                    int kp = (FEATD >> 1) + 2 * i;
                    const ulonglong2* wA = (const ulonglong2*)&w_s[kp * 32 + cg * 8];
                    const ulonglong2* wB = (const ulonglong2*)&w_s[kp * 32 + cg * 8 + 4];
                    const ulonglong2* wC = (const ulonglong2*)&w_s[(kp + 1) * 32 + cg * 8];
                    const ulonglong2* wD = (const ulonglong2*)&w_s[(kp + 1) * 32 + cg * 8 + 4];
                    ulonglong2 a = *wA, bq = *wB, cq = *wC, dq = *wD;
                    ffma2(acc0, av.x, a.x);  ffma2(acc1, av.x, a.y);
                    ffma2(acc2, av.x, bq.x); ffma2(acc3, av.x, bq.y);
                    ffma2(acc0, av.y, cq.x); ffma2(acc1, av.y, cq.y);
                    ffma2(acc2, av.y, dq.x); ffma2(acc3, av.y, dq.y);
                }
            }
            // ---- phase 1b: dec cols 2*blk,2*blk+1 (warp-coop rows) ---------
            {
#pragma unroll 2
                for (int r = 0; r < 8; r++) {
                    int bb = wid * 8 + r;
                    const float4* hv4 = (const float4*)(g_act[p] + bb * KTOT + FEATD);
                    float4 h0 = __ldcg(hv4 + l),      h1 = __ldcg(hv4 + l + 32);
                    float4 h2 = __ldcg(hv4 + l + 64), h3 = __ldcg(hv4 + l + 96);
#pragma unroll
                    for (int ci = 0; ci < 2; ci++) {
                        const float4* wv = (const float4*)(wdec + ci * HD);
                        float4 w0 = wv[l], w1 = wv[l + 32], w2 = wv[l + 64], w3 = wv[l + 96];
                        float s = h0.x*w0.x + h0.y*w0.y + h0.z*w0.z + h0.w*w0.w
                                + h1.x*w1.x + h1.y*w1.y + h1.z*w1.z + h1.w*w1.w
                                + h2.x*w2.x + h2.y*w2.y + h2.z*w2.z + h2.w*w2.w
                                + h3.x*w3.x + h3.y*w3.y + h3.z*w3.z + h3.w*w3.w;
                        s += __shfl_xor_sync(0xffffffffu, s, 16);
                        s += __shfl_xor_sync(0xffffffffu, s, 8);
                        s += __shfl_xor_sync(0xffffffffu, s, 4);
                        s += __shfl_xor_sync(0xffffffffu, s, 2);
                        s += __shfl_xor_sync(0xffffffffu, s, 1);
                        if (l == 0) {
                            int c = 2 * blk + ci;
                            __stcg(&g_dec[bb * DECD + c], tanhf(s + __ldg(&bhx[c])));
                        }
                    }
                }
            }
            gsync((++bar_n) * NB);

            // ---- phase 2: gate . feat(t) (K=256) + update ------------------
            {
                const ulonglong2* fv = (const ulonglong2*)(g_act[p] + b * KTOT);
#pragma unroll 8
                for (int i = 0; i < FEATD / 4; i++) {
                    ulonglong2 av = __ldcg(fv + i);
                    int kp = 2 * i;
                    const ulonglong2* wA = (const ulonglong2*)&w_s[kp * 32 + cg * 8];
                    const ulonglong2* wB = (const ulonglong2*)&w_s[kp * 32 + cg * 8 + 4];
                    const ulonglong2* wC = (const ulonglong2*)&w_s[(kp + 1) * 32 + cg * 8];
                    const ulonglong2* wD = (const ulonglong2*)&w_s[(kp + 1) * 32 + cg * 8 + 4];
                    ulonglong2 a = *wA, bq = *wB, cq = *wC, dq = *wD;
                    ffma2(acc0, av.x, a.x);  ffma2(acc1, av.x, a.y);
                    ffma2(acc2, av.x, bq.x); ffma2(acc3, av.x, bq.y);
                    ffma2(acc0, av.y, cq.x); ffma2(acc1, av.y, cq.y);
                    ffma2(acc2, av.y, dq.x); ffma2(acc3, av.y, dq.y);
                }
            }
            g_ex[b * 16 + cg * 4 + 0] = pairsum(acc0);
            g_ex[b * 16 + cg * 4 + 1] = pairsum(acc1);
            g_ex[b * 16 + cg * 4 + 2] = pairsum(acc2);
            g_ex[b * 16 + cg * 4 + 3] = pairsum(acc3);
            __syncthreads();
            {
                int u = cg;
                float i_v = g_ex[b * 16 + 0  + u];
                float f_v = g_ex[b * 16 + 4  + u];
                float gg  = g_ex[b * 16 + 8  + u];
                float o_v = g_ex[b * 16 + 12 + u];
                float c_new = sig_(f_v) * c_reg + sig_(i_v) * tanhf(gg);
                float h_new = sig_(o_v) * tanhf(c_new);
                c_reg = c_new;
                __stcg(&g_act[p ^ 1][b * KTOT + FEATD + n0 + u], h_new);
            }
            gsync((++bar_n) * NB);
        }
    } else {
        // ========================== F block =================================
        const int f = blk - NG;
        float* wfx_s  = smem;                 // [32][64]
        float* wout_s = smem + 32 * XD;       // [8][256]
        for (int idx = tid; idx < 32 * XD; idx += 256)
            wfx_s[idx] = Wfx[f * 32 * XD + idx];
        for (int idx = tid; idx < 8 * DECD; idx += 256)
            wout_s[idx] = Wout[f * 8 * DECD + idx];

        const int b  = tid & 63;
        const int ci = tid >> 6;              // 0..3

        gsync((++bar_n) * NB);

        for (int t = 0; t < SEQ; t++) {
            const int p = t & 1;
            // ---- phase 1: feat blend, cols f*32 .. f*32+31 -----------------
            {
                float yr[XD];
                if (t > 0) {
                    const float4* yv = (const float4*)(&g_yprev[b * XD]);
#pragma unroll
                    for (int k = 0; k < XD / 4; k++) {
                        float4 v = __ldcg(yv + k);
                        yr[4*k] = v.x; yr[4*k+1] = v.y; yr[4*k+2] = v.z; yr[4*k+3] = v.w;
                    }
                }
                float m = __ldg(&ms[t]);
#pragma unroll
                for (int q = 0; q < 8; q++) {
                    int cl = ci * 8 + q;
                    int c  = f * 32 + cl;
                    float ftf = __ldg(&g_feat_tf[(t * BATCH + b) * FEATD + c]);
                    float outv;
                    if (t == 0) {
                        outv = ftf;
                    } else {
                        float s = __ldg(&bfx[c]);
                        const float* w = wfx_s + cl * XD;
#pragma unroll
                        for (int k = 0; k < XD; k++) s += yr[k] * w[k];
                        outv = m * tanhf(s) + (1.0f - m) * ftf;
                    }
                    __stcg(&g_act[p][b * KTOT + c], outv);
                }
            }
            gsync((++bar_n) * NB);

            // ---- phase 2: y_t cols f*8..f*8+7 (warp-coop rows) -------------
            {
#pragma unroll 2
                for (int r = 0; r < 8; r++) {
                    int bb = wid * 8 + r;
                    const float4* dv = (const float4*)(g_dec + bb * DECD);
                    float4 d0 = __ldcg(dv + l), d1 = __ldcg(dv + l + 32);
#pragma unroll
                    for (int c = 0; c < 8; c++) {
                        const float4* wv = (const float4*)(wout_s + c * DECD);
                        float4 w0 = wv[l], w1 = wv[l + 32];
                        float s = d0.x*w0.x + d0.y*w0.y + d0.z*w0.z + d0.w*w0.w
                                + d1.x*w1.x + d1.y*w1.y + d1.z*w1.z + d1.w*w1.w;
                        s += __shfl_xor_sync(0xffffffffu, s, 16);
                        s += __shfl_xor_sync(0xffffffffu, s, 8);
                        s += __shfl_xor_sync(0xffffffffu, s, 4);
                        s += __shfl_xor_sync(0xffffffffu, s, 2);
                        s += __shfl_xor_sync(0xffffffffu, s, 1);
                        if (l == c) {
                            int cc = f * 8 + c;
                            float yv = s + __ldg(&bout[cc]);
                            out[(t * BATCH + bb) * XD + cc] = yv;
                            __stcg(&g_yprev[bb * XD + cc], yv);
                        }
                    }
                }
            }
            gsync((++bar_n) * NB);
        }
    }
}

// ---------------------------------------------------------------------------
extern "C" void kernel_launch(void* const* d_in, const int* in_sizes, int n_in,
                              void* d_out, int out_size) {
    const float* x    = (const float*)d_in[0];
    const float* ms   = (const float*)d_in[1];
    const float* Wfx  = (const float*)d_in[2];
    const float* bfx  = (const float*)d_in[3];
    const float* Wih  = (const float*)d_in[4];
    const float* Whh  = (const float*)d_in[5];
    const float* bih  = (const float*)d_in[6];
    const float* bhh  = (const float*)d_in[7];
    const float* Whx  = (const float*)d_in[8];
    const float* bhx  = (const float*)d_in[9];
    const float* Wout = (const float*)d_in[10];
    const float* bout = (const float*)d_in[11];
    float* out = (float*)d_out;

    const int smem_p = SM_FLOATS * sizeof(float);   // 57600 B
    static bool attr_set = false;
    if (!attr_set) {
        cudaFuncSetAttribute(k_persist, cudaFuncAttributeMaxDynamicSharedMemorySize, smem_p);
        attr_set = true;
    }

    k_reset<<<1, 1>>>();
    k_persist<<<NB, 256, smem_p>>>(x, ms, Wfx, bfx, Wih, Whh, bih, bhh,
                                   Whx, bhx, Wout, bout, out);
}

// round 7
// speedup vs baseline: 2.0547x; 1.0200x over previous
#include <cuda_runtime.h>
#include <math.h>

#define SEQ   256
#define BATCH 64
#define XD    64
#define FEATD 256
#define DECD  256
#define HD    512
#define KTOT  (FEATD + HD)   // 768
#define NG    128
#define NF    8
#define NB    (NG + NF)      // 136 blocks, all co-resident

// ---------------- persistent device scratch ---------------------------------
__device__ float g_feat_tf[SEQ * BATCH * FEATD];
__device__ float g_act[2][BATCH * KTOT];     // [feat(256) | h(512)]
__device__ float g_dec2[2][BATCH * DECD];    // double-buffered dec
// per-step flags: counter + separate read-only release flag
__device__ int c_dec[SEQ];  __device__ volatile int f_dec[SEQ];
__device__ int c_feat[SEQ]; __device__ volatile int f_feat[SEQ];
__device__ int c_h[SEQ];    __device__ volatile int f_h[SEQ];
__device__ int c_prol;      __device__ volatile int f_prol;

__device__ __forceinline__ float sig_(float x) { return 1.0f / (1.0f + expf(-x)); }

__device__ __forceinline__ void ffma2(unsigned long long& acc,
                                      unsigned long long a, unsigned long long b) {
    asm("fma.rn.f32x2 %0, %1, %2, %0;" : "+l"(acc) : "l"(a), "l"(b));
}
__device__ __forceinline__ float pairsum(unsigned long long v) {
    float lo, hi;
    asm("mov.b64 {%0,%1}, %2;" : "=f"(lo), "=f"(hi) : "l"(v));
    return lo + hi;
}
__device__ __forceinline__ unsigned long long pack2(float lo, float hi) {
    unsigned long long v;
    asm("mov.b64 %0, {%1,%2};" : "=l"(v) : "f"(lo), "f"(hi));
    return v;
}

// arrive: all block threads done -> one atomic; last arriver releases flag
__device__ __forceinline__ void blk_arrive(int* ct, volatile int* fl, int n) {
    __syncthreads();
    if (threadIdx.x == 0) {
        __threadfence();
        if (atomicAdd(ct, 1) == n - 1) *fl = 1;
    }
}
// wait: poll read-only flag line (not the atomic line)
__device__ __forceinline__ void blk_wait(volatile int* fl) {
    if (threadIdx.x == 0) {
        while (*fl == 0) __nanosleep(20);
    }
    __syncthreads();
}

__global__ void k_reset() {
    int i = threadIdx.x;
    for (int j = i; j < SEQ; j += 256) {
        c_dec[j] = 0;  f_dec[j] = 0;
        c_feat[j] = 0; f_feat[j] = 0;
        c_h[j] = 0;    f_h[j] = 0;
    }
    if (i == 0) { c_prol = 0; f_prol = 0; }
}

// smem float offsets (one dynamic allocation shared by G and F layouts)
// G: w_s[12288] | wdec[1024] | g_ex[1024]                (14336)
// F: wout_s[64*260=16640] | wfx_s[256*68=17408] | y_s[512]  (34560)
// XS (prologue x staging): 34560..34624
#define WOUT_OFF 0
#define WFX_OFF  16640
#define YS_OFF   34048
#define XS_OFF   34560
#define SM_FLOATS 34624

__global__ void __launch_bounds__(256, 1)
k_persist(const float* __restrict__ x,   const float* __restrict__ ms,
          const float* __restrict__ Wfx, const float* __restrict__ bfx,
          const float* __restrict__ Wih, const float* __restrict__ Whh,
          const float* __restrict__ bih, const float* __restrict__ bhh,
          const float* __restrict__ Whx, const float* __restrict__ bhx,
          const float* __restrict__ Wout,const float* __restrict__ bout,
          float* __restrict__ out) {
    extern __shared__ float smem[];
    const int blk = blockIdx.x;
    const int tid = threadIdx.x;
    const int wid = tid >> 5;
    const int l   = tid & 31;

    // ===================== prologue: feat_tf (all blocks) ====================
    {
        float wreg[XD];
        const float4* wf4 = (const float4*)(Wfx + tid * XD);
#pragma unroll
        for (int i = 0; i < XD / 4; i++) ((float4*)wreg)[i] = __ldg(wf4 + i);
        float biasf = __ldg(&bfx[tid]);
        float* xs = smem + XS_OFF;
        for (int r = blk; r < SEQ * BATCH; r += NB) {
            __syncthreads();
            if (tid < 16) ((float4*)xs)[tid] = __ldg((const float4*)(x + r * XD) + tid);
            __syncthreads();
            float s = biasf;
#pragma unroll
            for (int k = 0; k < XD; k++) s += xs[k] * wreg[k];
            g_feat_tf[r * FEATD + tid] = tanhf(s);
        }
        __syncthreads();
    }

    if (blk < NG) {
        // ========================== G block =================================
        float* w_s  = smem;                   // paired gate weights
        float* wdec = smem + KTOT * 16;       // [2][512]
        float* g_ex = wdec + 2 * HD;          // [64][16]
        const int n0 = blk * 4;

        for (int idx = tid; idx < KTOT * 16; idx += 256) {
            int k  = idx >> 4;
            int lc = idx & 15;
            int gi = lc >> 2;
            int u  = lc & 3;
            int j  = gi * HD + n0 + u;
            float v = (k < FEATD) ? Wih[j * FEATD + k] : Whh[j * HD + (k - FEATD)];
            w_s[(k >> 1) * 32 + lc * 2 + (k & 1)] = v;
        }
        for (int idx = tid; idx < 2 * HD; idx += 256)
            wdec[idx] = Whx[2 * blk * HD + idx];

        const int b  = tid >> 2;
        const int cg = tid & 3;
        const int jb = cg * HD + n0;
        const float bb0 = __ldg(&bih[jb + 0]) + __ldg(&bhh[jb + 0]);
        const float bb1 = __ldg(&bih[jb + 1]) + __ldg(&bhh[jb + 1]);
        const float bb2 = __ldg(&bih[jb + 2]) + __ldg(&bhh[jb + 2]);
        const float bb3 = __ldg(&bih[jb + 3]) + __ldg(&bhh[jb + 3]);
        const float bhx0 = __ldg(&bhx[2 * blk]);
        const float bhx1 = __ldg(&bhx[2 * blk + 1]);
        float c_reg = 0.0f;
        // zero h(0) (own units) before prologue barrier
        __stcg(&g_act[0][b * KTOT + FEATD + n0 + cg], 0.0f);

        blk_arrive(&c_prol, &f_prol, NB);
        blk_wait(&f_prol);

        for (int t = 0; t < SEQ; t++) {
            const int p = t & 1;
            if (t > 0) blk_wait(&f_h[t - 1]);     // h(t) published by all G

            // ---- phase 1a: gate . h(t)  (K=512, paired) --------------------
            unsigned long long acc0 = pack2(bb0, 0.f), acc1 = pack2(bb1, 0.f);
            unsigned long long acc2 = pack2(bb2, 0.f), acc3 = pack2(bb3, 0.f);
            {
                const ulonglong2* hv = (const ulonglong2*)(g_act[p] + b * KTOT + FEATD);
#pragma unroll 8
                for (int i = 0; i < HD / 4; i++) {
                    ulonglong2 av = __ldcg(hv + i);
                    int kp = (FEATD >> 1) + 2 * i;
                    const ulonglong2* wA = (const ulonglong2*)&w_s[kp * 32 + cg * 8];
                    const ulonglong2* wB = (const ulonglong2*)&w_s[kp * 32 + cg * 8 + 4];
                    const ulonglong2* wC = (const ulonglong2*)&w_s[(kp + 1) * 32 + cg * 8];
                    const ulonglong2* wD = (const ulonglong2*)&w_s[(kp + 1) * 32 + cg * 8 + 4];
                    ulonglong2 a = *wA, bq = *wB, cq = *wC, dq = *wD;
                    ffma2(acc0, av.x, a.x);  ffma2(acc1, av.x, a.y);
                    ffma2(acc2, av.x, bq.x); ffma2(acc3, av.x, bq.y);
                    ffma2(acc0, av.y, cq.x); ffma2(acc1, av.y, cq.y);
                    ffma2(acc2, av.y, dq.x); ffma2(acc3, av.y, dq.y);
                }
            }
            // ---- phase 1b: dec cols 2*blk,2*blk+1 (warp-coop rows) ---------
            {
#pragma unroll 2
                for (int r = 0; r < 8; r++) {
                    int bb = wid * 8 + r;
                    const float4* hv4 = (const float4*)(g_act[p] + bb * KTOT + FEATD);
                    float4 h0 = __ldcg(hv4 + l),      h1 = __ldcg(hv4 + l + 32);
                    float4 h2 = __ldcg(hv4 + l + 64), h3 = __ldcg(hv4 + l + 96);
#pragma unroll
                    for (int ci = 0; ci < 2; ci++) {
                        const float4* wv = (const float4*)(wdec + ci * HD);
                        float4 w0 = wv[l], w1 = wv[l + 32], w2 = wv[l + 64], w3 = wv[l + 96];
                        float s = h0.x*w0.x + h0.y*w0.y + h0.z*w0.z + h0.w*w0.w
                                + h1.x*w1.x + h1.y*w1.y + h1.z*w1.z + h1.w*w1.w
                                + h2.x*w2.x + h2.y*w2.y + h2.z*w2.z + h2.w*w2.w
                                + h3.x*w3.x + h3.y*w3.y + h3.z*w3.z + h3.w*w3.w;
                        s += __shfl_xor_sync(0xffffffffu, s, 16);
                        s += __shfl_xor_sync(0xffffffffu, s, 8);
                        s += __shfl_xor_sync(0xffffffffu, s, 4);
                        s += __shfl_xor_sync(0xffffffffu, s, 2);
                        s += __shfl_xor_sync(0xffffffffu, s, 1);
                        if (l == 0) {
                            float bias = ci ? bhx1 : bhx0;
                            __stcg(&g_dec2[p][bb * DECD + 2 * blk + ci], tanhf(s + bias));
                        }
                    }
                }
            }
            blk_arrive(&c_dec[t], &f_dec[t], NG);   // dec(t) published
            blk_wait(&f_feat[t]);                   // feat(t) from F (t=0: prologue)

            // ---- phase 2: gate . feat(t) (K=256) + update ------------------
            {
                const ulonglong2* fv = (const ulonglong2*)(g_act[p] + b * KTOT);
#pragma unroll 8
                for (int i = 0; i < FEATD / 4; i++) {
                    ulonglong2 av = __ldcg(fv + i);
                    int kp = 2 * i;
                    const ulonglong2* wA = (const ulonglong2*)&w_s[kp * 32 + cg * 8];
                    const ulonglong2* wB = (const ulonglong2*)&w_s[kp * 32 + cg * 8 + 4];
                    const ulonglong2* wC = (const ulonglong2*)&w_s[(kp + 1) * 32 + cg * 8];
                    const ulonglong2* wD = (const ulonglong2*)&w_s[(kp + 1) * 32 + cg * 8 + 4];
                    ulonglong2 a = *wA, bq = *wB, cq = *wC, dq = *wD;
                    ffma2(acc0, av.x, a.x);  ffma2(acc1, av.x, a.y);
                    ffma2(acc2, av.x, bq.x); ffma2(acc3, av.x, bq.y);
                    ffma2(acc0, av.y, cq.x); ffma2(acc1, av.y, cq.y);
                    ffma2(acc2, av.y, dq.x); ffma2(acc3, av.y, dq.y);
                }
            }
            g_ex[b * 16 + cg * 4 + 0] = pairsum(acc0);
            g_ex[b * 16 + cg * 4 + 1] = pairsum(acc1);
            g_ex[b * 16 + cg * 4 + 2] = pairsum(acc2);
            g_ex[b * 16 + cg * 4 + 3] = pairsum(acc3);
            __syncthreads();
            {
                int u = cg;
                float i_v = g_ex[b * 16 + 0  + u];
                float f_v = g_ex[b * 16 + 4  + u];
                float gg  = g_ex[b * 16 + 8  + u];
                float o_v = g_ex[b * 16 + 12 + u];
                float c_new = sig_(f_v) * c_reg + sig_(i_v) * tanhf(gg);
                float h_new = sig_(o_v) * tanhf(c_new);
                c_reg = c_new;
                __stcg(&g_act[p ^ 1][b * KTOT + FEATD + n0 + u], h_new);
            }
            blk_arrive(&c_h[t], &f_h[t], NG);       // h(t+1) published
        }
    } else {
        // ========================== F block =================================
        // self-contained: owns batches f*8 .. f*8+7; computes y(t) AND feat(t+1)
        const int f = blk - NG;
        float* wout_s = smem + WOUT_OFF;      // [64][260] padded
        float* wfx_s  = smem + WFX_OFF;       // [256][68] padded
        float* y_s    = smem + YS_OFF;        // [8][64]
        for (int idx = tid; idx < 64 * DECD; idx += 256) {
            int r = idx >> 8, cx = idx & 255;
            wout_s[r * 260 + cx] = Wout[idx];
        }
        for (int idx = tid; idx < FEATD * XD; idx += 256) {
            int r = idx >> 6, cx = idx & 63;
            wfx_s[r * 68 + cx] = Wfx[idx];
        }
        const int bg = f * 8 + wid;           // global batch this warp owns
        const float bo0 = __ldg(&bout[l]);
        const float bo1 = __ldg(&bout[l + 32]);

        blk_arrive(&c_prol, &f_prol, NB);
        blk_wait(&f_prol);

        // feat(0) = feat_tf[0] (blend identity at t=0)
        {
#pragma unroll
            for (int j = 0; j < 8; j++) {
                int c = l + 32 * j;
                __stcg(&g_act[0][bg * KTOT + c],
                       __ldg(&g_feat_tf[bg * FEATD + c]));
            }
        }
        blk_arrive(&c_feat[0], &f_feat[0], NF);

        for (int t = 0; t < SEQ; t++) {
            const int p = t & 1;
            blk_wait(&f_dec[t]);
            // ---- y(t) = dec(t) . Wout^T + bout : warp-per-batch ------------
            {
                const float4* dv = (const float4*)(g_dec2[p] + bg * DECD);
                const float4* w0v = (const float4*)(wout_s + l * 260);
                const float4* w1v = (const float4*)(wout_s + (l + 32) * 260);
                float s0 = 0.f, s1 = 0.f;
#pragma unroll 8
                for (int k4 = 0; k4 < DECD / 4; k4++) {
                    float4 d = __ldcg(dv + k4);       // broadcast (same addr warp-wide)
                    float4 a = w0v[k4], bq = w1v[k4];
                    s0 += d.x*a.x + d.y*a.y + d.z*a.z + d.w*a.w;
                    s1 += d.x*bq.x + d.y*bq.y + d.z*bq.z + d.w*bq.w;
                }
                float y0 = s0 + bo0, y1 = s1 + bo1;
                out[(t * BATCH + bg) * XD + l]      = y0;
                out[(t * BATCH + bg) * XD + l + 32] = y1;
                y_s[wid * 64 + l]      = y0;
                y_s[wid * 64 + l + 32] = y1;
                __syncwarp();
            }
            // ---- feat(t+1) = blend(tanh(y Wfx^T + bfx), feat_tf[t+1]) ------
            if (t + 1 < SEQ) {
                float m1 = __ldg(&ms[t + 1]);
                const float* yrow = y_s + wid * 64;
#pragma unroll
                for (int j = 0; j < 8; j++) {
                    int c = l + 32 * j;
                    const float4* wv = (const float4*)(wfx_s + c * 68);
                    float s = __ldg(&bfx[c]);
#pragma unroll
                    for (int k4 = 0; k4 < XD / 4; k4++) {
                        float4 yv = *(const float4*)(yrow + 4 * k4);  // broadcast
                        float4 wf = wv[k4];
                        s += yv.x*wf.x + yv.y*wf.y + yv.z*wf.z + yv.w*wf.w;
                    }
                    float ftf = __ldg(&g_feat_tf[((t + 1) * BATCH + bg) * FEATD + c]);
                    float v = m1 * tanhf(s) + (1.0f - m1) * ftf;
                    __stcg(&g_act[(t + 1) & 1][bg * KTOT + c], v);
                }
                blk_arrive(&c_feat[t + 1], &f_feat[t + 1], NF);
            }
        }
    }
}

// ---------------------------------------------------------------------------
extern "C" void kernel_launch(void* const* d_in, const int* in_sizes, int n_in,
                              void* d_out, int out_size) {
    const float* x    = (const float*)d_in[0];
    const float* ms   = (const float*)d_in[1];
    const float* Wfx  = (const float*)d_in[2];
    const float* bfx  = (const float*)d_in[3];
    const float* Wih  = (const float*)d_in[4];
    const float* Whh  = (const float*)d_in[5];
    const float* bih  = (const float*)d_in[6];
    const float* bhh  = (const float*)d_in[7];
    const float* Whx  = (const float*)d_in[8];
    const float* bhx  = (const float*)d_in[9];
    const float* Wout = (const float*)d_in[10];
    const float* bout = (const float*)d_in[11];
    float* out = (float*)d_out;

    const int smem_p = SM_FLOATS * sizeof(float);   // 138496 B
    static bool attr_set = false;
    if (!attr_set) {
        cudaFuncSetAttribute(k_persist, cudaFuncAttributeMaxDynamicSharedMemorySize, smem_p);
        attr_set = true;
    }

    k_reset<<<1, 256>>>();
    k_persist<<<NB, 256, smem_p>>>(x, ms, Wfx, bfx, Wih, Whh, bih, bhh,
                                   Whx, bhx, Wout, bout, out);
}

// round 9
// speedup vs baseline: 2.5361x; 1.2343x over previous
#include <cuda_runtime.h>
#include <math.h>

#define SEQ   256
#define BATCH 64
#define XD    64
#define FEATD 256
#define DECD  256
#define HD    512
#define KTOT  (FEATD + HD)   // 768
#define NG    128
#define NF    8
#define NB    (NG + NF)      // 136 blocks, all co-resident

// ---------------- persistent device scratch ---------------------------------
__device__ float g_feat_tf[SEQ * BATCH * FEATD];
__device__ float g_act[2][BATCH * KTOT];     // [feat(256) | h(512)]
__device__ float g_dec2[2][BATCH * DECD];    // double-buffered dec
__device__ int c_dec[SEQ];  __device__ volatile int f_dec[SEQ];
__device__ int c_feat[SEQ]; __device__ volatile int f_feat[SEQ];
__device__ int c_h[SEQ];    __device__ volatile int f_h[SEQ];
__device__ int c_prol;      __device__ volatile int f_prol;

__device__ __forceinline__ float sig_(float x) { return 1.0f / (1.0f + expf(-x)); }

__device__ __forceinline__ void ffma2(unsigned long long& acc,
                                      unsigned long long a, unsigned long long b) {
    asm("fma.rn.f32x2 %0, %1, %2, %0;" : "+l"(acc) : "l"(a), "l"(b));
}
__device__ __forceinline__ float pairsum(unsigned long long v) {
    float lo, hi;
    asm("mov.b64 {%0,%1}, %2;" : "=f"(lo), "=f"(hi) : "l"(v));
    return lo + hi;
}
__device__ __forceinline__ unsigned long long pack2(float lo, float hi) {
    unsigned long long v;
    asm("mov.b64 %0, {%1,%2};" : "=l"(v) : "f"(lo), "f"(hi));
    return v;
}

__device__ __forceinline__ void blk_arrive(int* ct, volatile int* fl, int n) {
    __syncthreads();
    if (threadIdx.x == 0) {
        __threadfence();
        if (atomicAdd(ct, 1) == n - 1) *fl = 1;
    }
}
__device__ __forceinline__ void blk_wait(volatile int* fl) {
    if (threadIdx.x == 0) {
        while (*fl == 0) __nanosleep(20);
    }
    __syncthreads();
}

__global__ void k_reset() {
    int i = threadIdx.x;
    for (int j = i; j < SEQ; j += 256) {
        c_dec[j] = 0;  f_dec[j] = 0;
        c_feat[j] = 0; f_feat[j] = 0;
        c_h[j] = 0;    f_h[j] = 0;
    }
    if (i == 0) { c_prol = 0; f_prol = 0; }
}

// smem float offsets
// G: w_s[12288] | wdec[1024] | g_ex[1024] | hs0[16640] | hs1[16640]  -> 47616
// F: wout_s[16640] | wfx_s[17408] | y_s[512]                         -> 34560
#define WS_OFF   0
#define WDEC_OFF 12288
#define GEX_OFF  13312
#define HS0_OFF  14336
#define HS1_OFF  30976
#define WOUT_OFF 0
#define WFX_OFF  16640
#define YS_OFF   34048
#define XS_OFF   47616
#define SM_FLOATS 47680
#define HSP 260   // padded row stride (bank-shift 4 per row)

__global__ void __launch_bounds__(256, 1)
k_persist(const float* __restrict__ x,   const float* __restrict__ ms,
          const float* __restrict__ Wfx, const float* __restrict__ bfx,
          const float* __restrict__ Wih, const float* __restrict__ Whh,
          const float* __restrict__ bih, const float* __restrict__ bhh,
          const float* __restrict__ Whx, const float* __restrict__ bhx,
          const float* __restrict__ Wout,const float* __restrict__ bout,
          float* __restrict__ out) {
    extern __shared__ float smem[];
    const int blk = blockIdx.x;
    const int tid = threadIdx.x;
    const int wid = tid >> 5;
    const int l   = tid & 31;

    // ===================== prologue: feat_tf (all blocks) ====================
    {
        float wreg[XD];
        const float4* wf4 = (const float4*)(Wfx + tid * XD);
#pragma unroll
        for (int i = 0; i < XD / 4; i++) ((float4*)wreg)[i] = __ldg(wf4 + i);
        float biasf = __ldg(&bfx[tid]);
        float* xs = smem + XS_OFF;
        for (int r = blk; r < SEQ * BATCH; r += NB) {
            __syncthreads();
            if (tid < 16) ((float4*)xs)[tid] = __ldg((const float4*)(x + r * XD) + tid);
            __syncthreads();
            float s = biasf;
#pragma unroll
            for (int k = 0; k < XD; k++) s += xs[k] * wreg[k];
            g_feat_tf[r * FEATD + tid] = tanhf(s);
        }
        __syncthreads();
    }

    if (blk < NG) {
        // ========================== G block =================================
        float* w_s  = smem + WS_OFF;
        float* wdec = smem + WDEC_OFF;
        float* g_ex = smem + GEX_OFF;
        float* hs0  = smem + HS0_OFF;
        float* hs1  = smem + HS1_OFF;
        const int n0 = blk * 4;

        for (int idx = tid; idx < KTOT * 16; idx += 256) {
            int k  = idx >> 4;
            int lc = idx & 15;
            int gi = lc >> 2;
            int u  = lc & 3;
            int j  = gi * HD + n0 + u;
            float v = (k < FEATD) ? Wih[j * FEATD + k] : Whh[j * HD + (k - FEATD)];
            w_s[(k >> 1) * 32 + lc * 2 + (k & 1)] = v;
        }
        for (int idx = tid; idx < 2 * HD; idx += 256)
            wdec[idx] = Whx[2 * blk * HD + idx];

        const int b  = tid >> 2;
        const int cg = tid & 3;
        const int jb = cg * HD + n0;
        const float bb0 = __ldg(&bih[jb + 0]) + __ldg(&bhh[jb + 0]);
        const float bb1 = __ldg(&bih[jb + 1]) + __ldg(&bhh[jb + 1]);
        const float bb2 = __ldg(&bih[jb + 2]) + __ldg(&bhh[jb + 2]);
        const float bb3 = __ldg(&bih[jb + 3]) + __ldg(&bhh[jb + 3]);
        const float bhx0 = __ldg(&bhx[2 * blk]);
        const float bhx1 = __ldg(&bhx[2 * blk + 1]);
        float c_reg = 0.0f;
        __stcg(&g_act[0][b * KTOT + FEATD + n0 + cg], 0.0f);

        blk_arrive(&c_prol, &f_prol, NB);
        blk_wait(&f_prol);

        for (int t = 0; t < SEQ; t++) {
            const int p = t & 1;
            if (t > 0) blk_wait(&f_h[t - 1]);

            // ---- stage h chunk0 (k 256..512) coalesced ---------------------
            {
                const float* src = g_act[p] + FEATD;
#pragma unroll
                for (int it = 0; it < 16; it++) {
                    int idx = it * 256 + tid;
                    int row = idx >> 6, col = idx & 63;
                    float4 v = __ldcg((const float4*)(src + row * KTOT) + col);
                    *(float4*)(hs0 + row * HSP + col * 4) = v;
                }
            }
            __syncthreads();
            // ---- stage h chunk1 (k 512..768) into hs1 (overlaps compute) ---
            {
                const float* src = g_act[p] + FEATD + 256;
#pragma unroll
                for (int it = 0; it < 16; it++) {
                    int idx = it * 256 + tid;
                    int row = idx >> 6, col = idx & 63;
                    float4 v = __ldcg((const float4*)(src + row * KTOT) + col);
                    *(float4*)(hs1 + row * HSP + col * 4) = v;
                }
            }

            unsigned long long acc0 = pack2(bb0, 0.f), acc1 = pack2(bb1, 0.f);
            unsigned long long acc2 = pack2(bb2, 0.f), acc3 = pack2(bb3, 0.f);
            float sd[8][2];
#pragma unroll
            for (int r = 0; r < 8; r++) { sd[r][0] = 0.f; sd[r][1] = 0.f; }

            // ---- compute on chunk0 (global k0 = 256) -----------------------
            {
                const ulonglong2* hv = (const ulonglong2*)(hs0 + b * HSP);
#pragma unroll 8
                for (int i = 0; i < 64; i++) {
                    ulonglong2 av = hv[i];
                    int kp = 128 + 2 * i;
                    ulonglong2 a  = *(const ulonglong2*)&w_s[kp * 32 + cg * 8];
                    ulonglong2 bq = *(const ulonglong2*)&w_s[kp * 32 + cg * 8 + 4];
                    ulonglong2 cq = *(const ulonglong2*)&w_s[(kp + 1) * 32 + cg * 8];
                    ulonglong2 dq = *(const ulonglong2*)&w_s[(kp + 1) * 32 + cg * 8 + 4];
                    ffma2(acc0, av.x, a.x);  ffma2(acc1, av.x, a.y);
                    ffma2(acc2, av.x, bq.x); ffma2(acc3, av.x, bq.y);
                    ffma2(acc0, av.y, cq.x); ffma2(acc1, av.y, cq.y);
                    ffma2(acc2, av.y, dq.x); ffma2(acc3, av.y, dq.y);
                }
#pragma unroll
                for (int r = 0; r < 8; r++) {
                    int bb = wid * 8 + r;
                    const float4* hv4 = (const float4*)(hs0 + bb * HSP);
                    float4 h0 = hv4[l], h1 = hv4[l + 32];
#pragma unroll
                    for (int ci = 0; ci < 2; ci++) {
                        const float4* wv = (const float4*)(wdec + ci * HD);
                        float4 w0 = wv[l], w1 = wv[l + 32];
                        sd[r][ci] += h0.x*w0.x + h0.y*w0.y + h0.z*w0.z + h0.w*w0.w
                                   + h1.x*w1.x + h1.y*w1.y + h1.z*w1.z + h1.w*w1.w;
                    }
                }
            }
            __syncthreads();   // hs1 ready
            // ---- compute on chunk1 (global k0 = 512) -----------------------
            {
                const ulonglong2* hv = (const ulonglong2*)(hs1 + b * HSP);
#pragma unroll 8
                for (int i = 0; i < 64; i++) {
                    ulonglong2 av = hv[i];
                    int kp = 256 + 2 * i;
                    ulonglong2 a  = *(const ulonglong2*)&w_s[kp * 32 + cg * 8];
                    ulonglong2 bq = *(const ulonglong2*)&w_s[kp * 32 + cg * 8 + 4];
                    ulonglong2 cq = *(const ulonglong2*)&w_s[(kp + 1) * 32 + cg * 8];
                    ulonglong2 dq = *(const ulonglong2*)&w_s[(kp + 1) * 32 + cg * 8 + 4];
                    ffma2(acc0, av.x, a.x);  ffma2(acc1, av.x, a.y);
                    ffma2(acc2, av.x, bq.x); ffma2(acc3, av.x, bq.y);
                    ffma2(acc0, av.y, cq.x); ffma2(acc1, av.y, cq.y);
                    ffma2(acc2, av.y, dq.x); ffma2(acc3, av.y, dq.y);
                }
#pragma unroll
                for (int r = 0; r < 8; r++) {
                    int bb = wid * 8 + r;
                    const float4* hv4 = (const float4*)(hs1 + bb * HSP);
                    float4 h0 = hv4[l], h1 = hv4[l + 32];
#pragma unroll
                    for (int ci = 0; ci < 2; ci++) {
                        const float4* wv = (const float4*)(wdec + ci * HD + 256);
                        float4 w0 = wv[l], w1 = wv[l + 32];
                        sd[r][ci] += h0.x*w0.x + h0.y*w0.y + h0.z*w0.z + h0.w*w0.w
                                   + h1.x*w1.x + h1.y*w1.y + h1.z*w1.z + h1.w*w1.w;
                    }
                }
            }
            // ---- finalize dec ---------------------------------------------
#pragma unroll
            for (int r = 0; r < 8; r++) {
#pragma unroll
                for (int ci = 0; ci < 2; ci++) {
                    float s = sd[r][ci];
                    s += __shfl_xor_sync(0xffffffffu, s, 16);
                    s += __shfl_xor_sync(0xffffffffu, s, 8);
                    s += __shfl_xor_sync(0xffffffffu, s, 4);
                    s += __shfl_xor_sync(0xffffffffu, s, 2);
                    s += __shfl_xor_sync(0xffffffffu, s, 1);
                    if (l == 0) {
                        int bb = wid * 8 + r;
                        float bias = ci ? bhx1 : bhx0;
                        __stcg(&g_dec2[p][bb * DECD + 2 * blk + ci], tanhf(s + bias));
                    }
                }
            }
            blk_arrive(&c_dec[t], &f_dec[t], NG);
            blk_wait(&f_feat[t]);

            // ---- stage feat chunk + gates final ----------------------------
            {
                const float* src = g_act[p];
#pragma unroll
                for (int it = 0; it < 16; it++) {
                    int idx = it * 256 + tid;
                    int row = idx >> 6, col = idx & 63;
                    float4 v = __ldcg((const float4*)(src + row * KTOT) + col);
                    *(float4*)(hs0 + row * HSP + col * 4) = v;
                }
            }
            __syncthreads();
            {
                const ulonglong2* hv = (const ulonglong2*)(hs0 + b * HSP);
#pragma unroll 8
                for (int i = 0; i < 64; i++) {
                    ulonglong2 av = hv[i];
                    int kp = 2 * i;
                    ulonglong2 a  = *(const ulonglong2*)&w_s[kp * 32 + cg * 8];
                    ulonglong2 bq = *(const ulonglong2*)&w_s[kp * 32 + cg * 8 + 4];
                    ulonglong2 cq = *(const ulonglong2*)&w_s[(kp + 1) * 32 + cg * 8];
                    ulonglong2 dq = *(const ulonglong2*)&w_s[(kp + 1) * 32 + cg * 8 + 4];
                    ffma2(acc0, av.x, a.x);  ffma2(acc1, av.x, a.y);
                    ffma2(acc2, av.x, bq.x); ffma2(acc3, av.x, bq.y);
                    ffma2(acc0, av.y, cq.x); ffma2(acc1, av.y, cq.y);
                    ffma2(acc2, av.y, dq.x); ffma2(acc3, av.y, dq.y);
                }
            }
            g_ex[b * 16 + cg * 4 + 0] = pairsum(acc0);
            g_ex[b * 16 + cg * 4 + 1] = pairsum(acc1);
            g_ex[b * 16 + cg * 4 + 2] = pairsum(acc2);
            g_ex[b * 16 + cg * 4 + 3] = pairsum(acc3);
            __syncthreads();
            {
                int u = cg;
                float i_v = g_ex[b * 16 + 0  + u];
                float f_v = g_ex[b * 16 + 4  + u];
                float gg  = g_ex[b * 16 + 8  + u];
                float o_v = g_ex[b * 16 + 12 + u];
                float c_new = sig_(f_v) * c_reg + sig_(i_v) * tanhf(gg);
                float h_new = sig_(o_v) * tanhf(c_new);
                c_reg = c_new;
                __stcg(&g_act[p ^ 1][b * KTOT + FEATD + n0 + u], h_new);
            }
            blk_arrive(&c_h[t], &f_h[t], NG);
        }
    } else {
        // ========================== F block =================================
        const int f = blk - NG;
        float* wout_s = smem + WOUT_OFF;
        float* wfx_s  = smem + WFX_OFF;
        float* y_s    = smem + YS_OFF;
        for (int idx = tid; idx < 64 * DECD; idx += 256) {
            int r = idx >> 8, cx = idx & 255;
            wout_s[r * 260 + cx] = Wout[idx];
        }
        for (int idx = tid; idx < FEATD * XD; idx += 256) {
            int r = idx >> 6, cx = idx & 63;
            wfx_s[r * 68 + cx] = Wfx[idx];
        }
        const int bg = f * 8 + wid;
        const float bo0 = __ldg(&bout[l]);
        const float bo1 = __ldg(&bout[l + 32]);

        blk_arrive(&c_prol, &f_prol, NB);
        blk_wait(&f_prol);

        {
#pragma unroll
            for (int j = 0; j < 8; j++) {
                int c = l + 32 * j;
                __stcg(&g_act[0][bg * KTOT + c],
                       __ldg(&g_feat_tf[bg * FEATD + c]));
            }
        }
        blk_arrive(&c_feat[0], &f_feat[0], NF);

        for (int t = 0; t < SEQ; t++) {
            const int p = t & 1;
            blk_wait(&f_dec[t]);
            {
                const float4* dv = (const float4*)(g_dec2[p] + bg * DECD);
                const float4* w0v = (const float4*)(wout_s + l * 260);
                const float4* w1v = (const float4*)(wout_s + (l + 32) * 260);
                float s0 = 0.f, s1 = 0.f;
#pragma unroll 8
                for (int k4 = 0; k4 < DECD / 4; k4++) {
                    float4 d = __ldcg(dv + k4);
                    float4 a = w0v[k4], bq = w1v[k4];
                    s0 += d.x*a.x + d.y*a.y + d.z*a.z + d.w*a.w;
                    s1 += d.x*bq.x + d.y*bq.y + d.z*bq.z + d.w*bq.w;
                }
                float y0 = s0 + bo0, y1 = s1 + bo1;
                out[(t * BATCH + bg) * XD + l]      = y0;
                out[(t * BATCH + bg) * XD + l + 32] = y1;
                y_s[wid * 64 + l]      = y0;
                y_s[wid * 64 + l + 32] = y1;
                __syncwarp();
            }
            if (t + 1 < SEQ) {
                float m1 = __ldg(&ms[t + 1]);
                const float* yrow = y_s + wid * 64;
#pragma unroll
                for (int j = 0; j < 8; j++) {
                    int c = l + 32 * j;
                    const float4* wv = (const float4*)(wfx_s + c * 68);
                    float s = __ldg(&bfx[c]);
#pragma unroll
                    for (int k4 = 0; k4 < XD / 4; k4++) {
                        float4 yv = *(const float4*)(yrow + 4 * k4);
                        float4 wf = wv[k4];
                        s += yv.x*wf.x + yv.y*wf.y + yv.z*wf.z + yv.w*wf.w;
                    }
                    float ftf = __ldg(&g_feat_tf[((t + 1) * BATCH + bg) * FEATD + c]);
                    float v = m1 * tanhf(s) + (1.0f - m1) * ftf;
                    __stcg(&g_act[(t + 1) & 1][bg * KTOT + c], v);
                }
                blk_arrive(&c_feat[t + 1], &f_feat[t + 1], NF);
            }
        }
    }
}

// ---------------------------------------------------------------------------
extern "C" void kernel_launch(void* const* d_in, const int* in_sizes, int n_in,
                              void* d_out, int out_size) {
    const float* x    = (const float*)d_in[0];
    const float* ms   = (const float*)d_in[1];
    const float* Wfx  = (const float*)d_in[2];
    const float* bfx  = (const float*)d_in[3];
    const float* Wih  = (const float*)d_in[4];
    const float* Whh  = (const float*)d_in[5];
    const float* bih  = (const float*)d_in[6];
    const float* bhh  = (const float*)d_in[7];
    const float* Whx  = (const float*)d_in[8];
    const float* bhx  = (const float*)d_in[9];
    const float* Wout = (const float*)d_in[10];
    const float* bout = (const float*)d_in[11];
    float* out = (float*)d_out;

    const int smem_p = SM_FLOATS * sizeof(float);   // 190720 B
    static bool attr_set = false;
    if (!attr_set) {
        cudaFuncSetAttribute(k_persist, cudaFuncAttributeMaxDynamicSharedMemorySize, smem_p);
        attr_set = true;
    }

    k_reset<<<1, 256>>>();
    k_persist<<<NB, 256, smem_p>>>(x, ms, Wfx, bfx, Wih, Whh, bih, bhh,
                                   Whx, bhx, Wout, bout, out);
}